// round 1
// baseline (speedup 1.0000x reference)
#include <cuda_runtime.h>
#include <cstdint>

#define DDIM 768
#define NMAX 4096
#define KMAX 65536

// Scratch (no allocations allowed): argmin keys, loss accumulator, row norms.
__device__ unsigned long long g_minkey[NMAX];
__device__ double g_loss;
__device__ float g_zsq[NMAX];
__device__ float g_esq[KMAX];

// ---------------------------------------------------------------------------
// Init scratch each launch (graph-capturable, deterministic).
// ---------------------------------------------------------------------------
__global__ void init_kernel() {
    int i = blockIdx.x * blockDim.x + threadIdx.x;
    if (i < NMAX) g_minkey[i] = ~0ULL;
    if (i == 0) g_loss = 0.0;
}

// ---------------------------------------------------------------------------
// Row squared norms. Accumulation is STRICTLY SEQUENTIAL over the 768 dim to
// mirror jnp.sum(x*x, axis=-1): products rounded, then left-to-right adds.
// (z_sq's exact bits set the fp32 rounding-grid phase near 768 and thereby
// the reference's tie pattern — this is the precision-critical piece.)
// ---------------------------------------------------------------------------
__global__ void zsq_kernel(const float* __restrict__ X, int rows) {
    int r = blockIdx.x * blockDim.x + threadIdx.x;
    if (r >= rows) return;
    const float4* x = reinterpret_cast<const float4*>(X + (size_t)r * DDIM);
    float s = 0.f;
#pragma unroll 4
    for (int i = 0; i < DDIM / 4; i++) {
        float4 v = __ldg(&x[i]);
        s = __fadd_rn(s, __fmul_rn(v.x, v.x));
        s = __fadd_rn(s, __fmul_rn(v.y, v.y));
        s = __fadd_rn(s, __fmul_rn(v.z, v.z));
        s = __fadd_rn(s, __fmul_rn(v.w, v.w));
    }
    g_zsq[r] = s;
}

__global__ void esq_kernel(const float* __restrict__ X, int rows) {
    int r = blockIdx.x * blockDim.x + threadIdx.x;
    if (r >= rows) return;
    const float4* x = reinterpret_cast<const float4*>(X + (size_t)r * DDIM);
    float s = 0.f;
#pragma unroll 4
    for (int i = 0; i < DDIM / 4; i++) {
        float4 v = __ldg(&x[i]);
        s = __fadd_rn(s, __fmul_rn(v.x, v.x));
        s = __fadd_rn(s, __fmul_rn(v.y, v.y));
        s = __fadd_rn(s, __fmul_rn(v.z, v.z));
        s = __fadd_rn(s, __fmul_rn(v.w, v.w));
    }
    g_esq[r] = s;
}

// ---------------------------------------------------------------------------
// Fused SGEMM + quantized-distance argmin.
// Tile: 128x128, BK=16, 256 threads, 8x8 per-thread microtile (fp32 FFMA).
// Epilogue replicates the reference rounding:
//   d = fl( fl(zsq[r] + esq[c]) - fl(2*dot) )   (2*dot exact; fsub rounds)
// Tie-break to lowest index via uint64 key = (bits(d)<<32)|c and atomicMin.
// ---------------------------------------------------------------------------
#define BM 128
#define BN 128
#define BK 16
#define TM 8
#define TN 8

__global__ __launch_bounds__(256, 2)
void vq_gemm_argmin_kernel(const float* __restrict__ A,   // N x 768 embeddings
                           const float* __restrict__ B) { // K x 768 codebook
    __shared__ float As[BK][BM + 4];
    __shared__ float Bs[BK][BN + 4];
    __shared__ unsigned long long sMin[BM];

    const int bm = blockIdx.y * BM;
    const int bn = blockIdx.x * BN;
    const int tid = threadIdx.x;
    const int tx = tid & 15;
    const int ty = tid >> 4;

    if (tid < BM) sMin[tid] = ~0ULL;

    float acc[TM][TN];
#pragma unroll
    for (int i = 0; i < TM; i++)
#pragma unroll
        for (int j = 0; j < TN; j++) acc[i][j] = 0.f;

    for (int k0 = 0; k0 < DDIM; k0 += BK) {
        // Each thread loads 2 float4 for A-tile and 2 for B-tile.
#pragma unroll
        for (int pp = 0; pp < 2; pp++) {
            int p = tid + pp * 256;     // [0, 512)
            int row = p >> 2;           // 0..127
            int cq = p & 3;             // 4-float column group
            float4 v = *reinterpret_cast<const float4*>(
                &A[(size_t)(bm + row) * DDIM + k0 + cq * 4]);
            As[cq * 4 + 0][row] = v.x;
            As[cq * 4 + 1][row] = v.y;
            As[cq * 4 + 2][row] = v.z;
            As[cq * 4 + 3][row] = v.w;
            float4 w = *reinterpret_cast<const float4*>(
                &B[(size_t)(bn + row) * DDIM + k0 + cq * 4]);
            Bs[cq * 4 + 0][row] = w.x;
            Bs[cq * 4 + 1][row] = w.y;
            Bs[cq * 4 + 2][row] = w.z;
            Bs[cq * 4 + 3][row] = w.w;
        }
        __syncthreads();

#pragma unroll
        for (int kk = 0; kk < BK; kk++) {
            float a[TM], b[TN];
            float4 a0 = *reinterpret_cast<const float4*>(&As[kk][ty * TM]);
            float4 a1 = *reinterpret_cast<const float4*>(&As[kk][ty * TM + 4]);
            a[0] = a0.x; a[1] = a0.y; a[2] = a0.z; a[3] = a0.w;
            a[4] = a1.x; a[5] = a1.y; a[6] = a1.z; a[7] = a1.w;
            float4 b0 = *reinterpret_cast<const float4*>(&Bs[kk][tx * TN]);
            float4 b1 = *reinterpret_cast<const float4*>(&Bs[kk][tx * TN + 4]);
            b[0] = b0.x; b[1] = b0.y; b[2] = b0.z; b[3] = b0.w;
            b[4] = b1.x; b[5] = b1.y; b[6] = b1.z; b[7] = b1.w;
#pragma unroll
            for (int i = 0; i < TM; i++)
#pragma unroll
                for (int j = 0; j < TN; j++)
                    acc[i][j] = __fmaf_rn(a[i], b[j], acc[i][j]);
        }
        __syncthreads();
    }

    // Epilogue: quantized distances + per-row argmin (tie -> lowest index).
#pragma unroll
    for (int i = 0; i < TM; i++) {
        int r = ty * TM + i;
        float zq = g_zsq[bm + r];
        unsigned long long best = ~0ULL;
#pragma unroll
        for (int j = 0; j < TN; j++) {
            int c = bn + tx * TN + j;
            float anchor = __fadd_rn(zq, g_esq[c]);           // fl(z2 + e2)
            float twodot = __fadd_rn(acc[i][j], acc[i][j]);   // exact 2*dot
            float dist = __fsub_rn(anchor, twodot);           // fl(a - 2d)
            unsigned long long key =
                ((unsigned long long)__float_as_uint(dist) << 32) |
                (unsigned long long)(unsigned)c;
            best = key < best ? key : best;
        }
        atomicMin(&sMin[r], best);
    }
    __syncthreads();
    if (tid < BM) atomicMin(&g_minkey[bm + tid], sMin[tid]);
}

// ---------------------------------------------------------------------------
// Finalize: codes (as float), straight-through output ste = fl(z + fl(q - z))
// (replicated bitwise vs reference), and loss partial sums.
// ---------------------------------------------------------------------------
__global__ void finalize_kernel(const float* __restrict__ A,
                                const float* __restrict__ B,
                                float* __restrict__ out_codes,
                                float* __restrict__ out_q) {
    int n = blockIdx.x;
    int code = (int)(g_minkey[n] & 0xFFFFFFFFULL);
    if (threadIdx.x == 0) out_codes[n] = (float)code;

    const float* q = B + (size_t)code * DDIM;
    const float* z = A + (size_t)n * DDIM;
    float ls = 0.f;
    for (int i = threadIdx.x; i < DDIM; i += blockDim.x) {
        float qv = q[i];
        float zv = z[i];
        out_q[(size_t)n * DDIM + i] = __fadd_rn(zv, __fsub_rn(qv, zv));
        float d = zv - qv;
        ls = __fmaf_rn(d, d, ls);
    }
    // block reduce
#pragma unroll
    for (int o = 16; o > 0; o >>= 1) ls += __shfl_xor_sync(0xFFFFFFFFu, ls, o);
    __shared__ float wsum[8];
    int wid = threadIdx.x >> 5;
    if ((threadIdx.x & 31) == 0) wsum[wid] = ls;
    __syncthreads();
    if (threadIdx.x == 0) {
        float s = 0.f;
        int nw = blockDim.x >> 5;
        for (int w = 0; w < nw; w++) s += wsum[w];
        atomicAdd(&g_loss, (double)s);
    }
}

__global__ void loss_kernel(float* __restrict__ out_loss, double inv_nd) {
    if (threadIdx.x == 0)
        out_loss[0] = (float)(g_loss * inv_nd * 1.25);
}

// ---------------------------------------------------------------------------
extern "C" void kernel_launch(void* const* d_in, const int* in_sizes, int n_in,
                              void* d_out, int out_size) {
    const float* A = (const float*)d_in[0];  // embeddings (B*L*768)
    const float* B = (const float*)d_in[1];  // codebook (K*768)
    const int N = in_sizes[0] / DDIM;        // 4096
    const int K = in_sizes[1] / DDIM;        // 65536

    float* out = (float*)d_out;
    float* out_codes = out;                   // [N]
    float* out_q = out + N;                   // [N*768]
    float* out_loss = out + N + (size_t)N * DDIM;  // [1]

    init_kernel<<<(NMAX + 255) / 256, 256>>>();
    zsq_kernel<<<(N + 127) / 128, 128>>>(A, N);
    esq_kernel<<<(K + 127) / 128, 128>>>(B, K);

    dim3 grid(K / BN, N / BM);   // (512, 32)
    vq_gemm_argmin_kernel<<<grid, 256>>>(A, B);

    finalize_kernel<<<N, 256>>>(A, B, out_codes, out_q);
    loss_kernel<<<1, 32>>>(out_loss, 1.0 / ((double)N * (double)DDIM));
}

// round 3
// speedup vs baseline: 5.9292x; 5.9292x over previous
#include <cuda_runtime.h>
#include <cuda_bf16.h>
#include <cstdint>

#define DDIM 768
#define NQ   4096
#define KC   65536
#define BM   128
#define BN   128
#define BK   64
#define NSTAGE (DDIM / BK)   // 12
#define CAP  2048
#define MARGIN 2.0e-4f

// ---------------------------------------------------------------------------
// Device scratch (static — no allocations allowed)
// ---------------------------------------------------------------------------
__device__ float g_zsq[NQ];
__device__ float g_esq[KC];
__device__ __nv_bfloat16 g_Abf[(size_t)NQ * DDIM];   // 6 MB
__device__ __nv_bfloat16 g_Bbf[(size_t)KC * DDIM];   // 100 MB
__device__ unsigned int g_rowmin[NQ];                // ordered-uint encoded float
__device__ int g_cnt[NQ];
__device__ int g_cand[(size_t)NQ * CAP];             // 32 MB
__device__ double g_loss;

// ---------------------------------------------------------------------------
// Helpers
// ---------------------------------------------------------------------------
__device__ __forceinline__ uint32_t smem_u32(const void* p) {
    uint32_t a;
    asm("{ .reg .u64 t; cvta.to.shared.u64 t, %1; cvt.u32.u64 %0, t; }"
        : "=r"(a) : "l"(p));
    return a;
}
#define SW128(off) ((off) ^ (((off) >> 3) & 0x70))
#define CP16(dst, src) \
    asm volatile("cp.async.cg.shared.global [%0], [%1], 16;" :: "r"(dst), "l"(src))
#define CP_COMMIT() asm volatile("cp.async.commit_group;" ::: "memory")
#define CP_WAIT(n)  asm volatile("cp.async.wait_group %0;" :: "n"(n) : "memory")

__device__ __forceinline__ void ldm_x4(uint32_t& r0, uint32_t& r1, uint32_t& r2,
                                       uint32_t& r3, uint32_t addr) {
    asm volatile("ldmatrix.sync.aligned.m8n8.x4.shared.b16 {%0,%1,%2,%3}, [%4];"
                 : "=r"(r0), "=r"(r1), "=r"(r2), "=r"(r3) : "r"(addr));
}
__device__ __forceinline__ void mma_bf16(float* d, const uint32_t* a,
                                         uint32_t b0, uint32_t b1) {
    asm volatile(
        "mma.sync.aligned.m16n8k16.row.col.f32.bf16.bf16.f32 "
        "{%0,%1,%2,%3}, {%4,%5,%6,%7}, {%8,%9}, {%0,%1,%2,%3};"
        : "+f"(d[0]), "+f"(d[1]), "+f"(d[2]), "+f"(d[3])
        : "r"(a[0]), "r"(a[1]), "r"(a[2]), "r"(a[3]), "r"(b0), "r"(b1));
}

// float <-> ordered uint (for atomicMin over signed floats)
__device__ __forceinline__ unsigned fenc(float f) {
    unsigned u = __float_as_uint(f);
    return (u & 0x80000000u) ? ~u : (u | 0x80000000u);
}
__device__ __forceinline__ float fdec(unsigned u) {
    return (u & 0x80000000u) ? __uint_as_float(u & 0x7FFFFFFFu)
                             : __uint_as_float(~u);
}

// ---------------------------------------------------------------------------
// Init / norms / convert
// ---------------------------------------------------------------------------
__global__ void init_kernel() {
    int i = blockIdx.x * blockDim.x + threadIdx.x;
    if (i < NQ) { g_rowmin[i] = 0xFFFFFFFFu; g_cnt[i] = 0; }
    if (i == 0) g_loss = 0.0;
}

// strictly-sequential fp32 norms: fl(mul) then fl(add) — validated recipe
__global__ void sqnorm_kernel(const float* __restrict__ X, float* __restrict__ out,
                              int rows) {
    int r = blockIdx.x * blockDim.x + threadIdx.x;
    if (r >= rows) return;
    const float4* x = reinterpret_cast<const float4*>(X + (size_t)r * DDIM);
    float s = 0.f;
#pragma unroll 4
    for (int i = 0; i < DDIM / 4; i++) {
        float4 v = __ldg(&x[i]);
        s = __fadd_rn(s, __fmul_rn(v.x, v.x));
        s = __fadd_rn(s, __fmul_rn(v.y, v.y));
        s = __fadd_rn(s, __fmul_rn(v.z, v.z));
        s = __fadd_rn(s, __fmul_rn(v.w, v.w));
    }
    out[r] = s;
}

__global__ void convert_kernel(const float* __restrict__ X,
                               __nv_bfloat16* __restrict__ out, size_t n) {
    size_t i = ((size_t)blockIdx.x * blockDim.x + threadIdx.x) * 4;
    if (i >= n) return;
    float4 v = *reinterpret_cast<const float4*>(X + i);
    out[i + 0] = __float2bfloat16(v.x);
    out[i + 1] = __float2bfloat16(v.y);
    out[i + 2] = __float2bfloat16(v.z);
    out[i + 3] = __float2bfloat16(v.w);
}

// ---------------------------------------------------------------------------
// Pass 1: bf16 HMMA GEMM (128x128 tile, K=768) + score prune.
//   score s~ = esq[c] - 2*dot~ ; collect c with s~ <= runningRowMin + MARGIN
// ---------------------------------------------------------------------------
__global__ void __launch_bounds__(256, 2) pass1_kernel() {
    extern __shared__ char smem[];
    const uint32_t sb = smem_u32(smem);
    // layout: A[0] 16K | A[1] 16K | B[0] 16K | B[1] 16K
    const uint32_t A_S[2] = {sb, sb + 16384};
    const uint32_t B_S[2] = {sb + 32768, sb + 49152};

    const int tid = threadIdx.x;
    const int wid = tid >> 5;
    const int lane = tid & 31;
    const int warp_m = wid >> 2;       // 0..1
    const int warp_n = wid & 3;        // 0..3
    const int bm = blockIdx.x * BM;
    const int bn = blockIdx.y * BN;

    float acc[4][4][4];
#pragma unroll
    for (int i = 0; i < 4; i++)
#pragma unroll
        for (int j = 0; j < 4; j++)
#pragma unroll
            for (int t = 0; t < 4; t++) acc[i][j][t] = 0.f;

    auto fill = [&](int stg, int s) {
#pragma unroll
        for (int i = 0; i < 4; i++) {
            int idx = tid + i * 256;          // 0..1023
            int row = idx >> 3, ch = idx & 7;
            const __nv_bfloat16* srcA = g_Abf + (size_t)(bm + row) * DDIM + s * BK + ch * 8;
            CP16(A_S[stg] + SW128(row * 128 + ch * 16), srcA);
            const __nv_bfloat16* srcB = g_Bbf + (size_t)(bn + row) * DDIM + s * BK + ch * 8;
            CP16(B_S[stg] + SW128(row * 128 + ch * 16), srcB);
        }
        CP_COMMIT();
    };

    fill(0, 0);
    fill(1, 1);

    // per-lane ldmatrix source rows (constant across k-steps)
    const int a_r = warp_m * 64 + (lane & 7) + ((lane & 8) ? 8 : 0);  // + mi*16
    const int b_r = warp_n * 32 + (lane & 7) + ((lane & 8) ? 8 : 0);  // + bj*16
    const int chk = (lane >> 4) & 1;                                   // k-half

    for (int s = 0; s < NSTAGE; s++) {
        if (s < NSTAGE - 1) { CP_WAIT(1); } else { CP_WAIT(0); }
        __syncthreads();
        const uint32_t Ab = A_S[s & 1], Bb = B_S[s & 1];
#pragma unroll
        for (int kk = 0; kk < 4; kk++) {
            const int ch = chk + kk * 2;
            uint32_t a[4][4];
#pragma unroll
            for (int mi = 0; mi < 4; mi++) {
                int r = a_r + mi * 16;
                ldm_x4(a[mi][0], a[mi][1], a[mi][2], a[mi][3],
                       Ab + (uint32_t)(r * 128 + ((ch * 16) ^ ((r & 7) << 4))));
            }
            uint32_t bf[2][4];
#pragma unroll
            for (int bj = 0; bj < 2; bj++) {
                int r = b_r + bj * 16;
                ldm_x4(bf[bj][0], bf[bj][1], bf[bj][2], bf[bj][3],
                       Bb + (uint32_t)(r * 128 + ((ch * 16) ^ ((r & 7) << 4))));
            }
#pragma unroll
            for (int mi = 0; mi < 4; mi++)
#pragma unroll
                for (int nj = 0; nj < 4; nj++)
                    mma_bf16(acc[mi][nj], a[mi], bf[nj >> 1][nj & 1],
                             bf[nj >> 1][2 + (nj & 1)]);
        }
        __syncthreads();
        if (s + 2 < NSTAGE) fill(s & 1, s + 2);
    }

    // ---- epilogue: scores, running row-min, candidate collection ----
#pragma unroll
    for (int mi = 0; mi < 4; mi++) {
#pragma unroll
        for (int half = 0; half < 2; half++) {
            const int row = bm + warp_m * 64 + mi * 16 + (lane >> 2) + half * 8;
            float rmin = 3.4e38f;
            float sc[4][2];
#pragma unroll
            for (int nj = 0; nj < 4; nj++)
#pragma unroll
                for (int t = 0; t < 2; t++) {
                    int c = bn + warp_n * 32 + nj * 8 + (lane & 3) * 2 + t;
                    float v = __fmaf_rn(-2.f, acc[mi][nj][half * 2 + t], g_esq[c]);
                    sc[nj][t] = v;
                    rmin = fminf(rmin, v);
                }
            // quad-reduce min (lanes l^1, l^2 share the row)
            rmin = fminf(rmin, __shfl_xor_sync(0xFFFFFFFFu, rmin, 1));
            rmin = fminf(rmin, __shfl_xor_sync(0xFFFFFFFFu, rmin, 2));
            unsigned enc = fenc(rmin);
            unsigned old = 0xFFFFFFFFu;
            if ((lane & 3) == 0) old = atomicMin(&g_rowmin[row], enc);
            old = __shfl_sync(0xFFFFFFFFu, old, lane & ~3);
            float T = fdec(old < enc ? old : enc) + MARGIN;
#pragma unroll
            for (int nj = 0; nj < 4; nj++)
#pragma unroll
                for (int t = 0; t < 2; t++) {
                    if (sc[nj][t] <= T) {
                        int c = bn + warp_n * 32 + nj * 8 + (lane & 3) * 2 + t;
                        int pos = atomicAdd(&g_cnt[row], 1);
                        if (pos < CAP) g_cand[(size_t)row * CAP + pos] = c;
                    }
                }
        }
    }
}

// ---------------------------------------------------------------------------
// Pass 2: exact re-rank of candidates (bit-identical round-1 recipe),
// then codes / STE / loss. One block per row.
// ---------------------------------------------------------------------------
__global__ void finalize_kernel(const float* __restrict__ A,
                                const float* __restrict__ B,
                                float* __restrict__ out_codes,
                                float* __restrict__ out_q) {
    __shared__ unsigned long long sKey;
    const int n = blockIdx.x;
    if (threadIdx.x == 0) sKey = ~0ULL;
    __syncthreads();

    const float zq = g_zsq[n];
    const float* z = A + (size_t)n * DDIM;
    int cnt = g_cnt[n];
    if (cnt > CAP) cnt = CAP;

    unsigned long long best = ~0ULL;
    for (int i = threadIdx.x; i < cnt; i += blockDim.x) {
        int c = g_cand[(size_t)n * CAP + i];
        const float4* e4 = reinterpret_cast<const float4*>(B + (size_t)c * DDIM);
        const float4* z4 = reinterpret_cast<const float4*>(z);
        float dot = 0.f;
#pragma unroll 4
        for (int k = 0; k < DDIM / 4; k++) {
            float4 ev = __ldg(&e4[k]);
            float4 zv = __ldg(&z4[k]);
            dot = __fmaf_rn(zv.x, ev.x, dot);
            dot = __fmaf_rn(zv.y, ev.y, dot);
            dot = __fmaf_rn(zv.z, ev.z, dot);
            dot = __fmaf_rn(zv.w, ev.w, dot);
        }
        float anchor = __fadd_rn(zq, g_esq[c]);               // fl(z2 + e2)
        float dist = __fsub_rn(anchor, __fadd_rn(dot, dot));  // fl(a - 2*dot)
        unsigned long long key =
            ((unsigned long long)__float_as_uint(dist) << 32) |
            (unsigned long long)(unsigned)c;
        best = key < best ? key : best;
    }
    atomicMin(&sKey, best);
    __syncthreads();

    const int code = (int)(sKey & 0xFFFFFFFFULL);
    if (threadIdx.x == 0) out_codes[n] = (float)code;

    const float* q = B + (size_t)code * DDIM;
    float ls = 0.f;
    for (int i = threadIdx.x; i < DDIM; i += blockDim.x) {
        float qv = q[i];
        float zv = z[i];
        out_q[(size_t)n * DDIM + i] = __fadd_rn(zv, __fsub_rn(qv, zv));
        float d = zv - qv;
        ls = __fmaf_rn(d, d, ls);
    }
#pragma unroll
    for (int o = 16; o > 0; o >>= 1) ls += __shfl_xor_sync(0xFFFFFFFFu, ls, o);
    __shared__ float wsum[8];
    int w = threadIdx.x >> 5;
    if ((threadIdx.x & 31) == 0) wsum[w] = ls;
    __syncthreads();
    if (threadIdx.x == 0) {
        float s = 0.f;
        for (int k = 0; k < (int)(blockDim.x >> 5); k++) s += wsum[k];
        atomicAdd(&g_loss, (double)s);
    }
}

__global__ void loss_kernel(float* __restrict__ out_loss, double inv_nd) {
    if (threadIdx.x == 0) out_loss[0] = (float)(g_loss * inv_nd * 1.25);
}

// ---------------------------------------------------------------------------
extern "C" void kernel_launch(void* const* d_in, const int* in_sizes, int n_in,
                              void* d_out, int out_size) {
    const float* A = (const float*)d_in[0];  // embeddings (4096 x 768)
    const float* B = (const float*)d_in[1];  // codebook  (65536 x 768)
    const int N = in_sizes[0] / DDIM;
    const int K = in_sizes[1] / DDIM;

    float* out = (float*)d_out;
    float* out_codes = out;
    float* out_q = out + N;
    float* out_loss = out + N + (size_t)N * DDIM;

    static const int SMEM_BYTES = 65536;
    cudaFuncSetAttribute(pass1_kernel, cudaFuncAttributeMaxDynamicSharedMemorySize,
                         SMEM_BYTES);

    init_kernel<<<(NQ + 255) / 256, 256>>>();

    float* zsq_p; cudaGetSymbolAddress((void**)&zsq_p, g_zsq);
    float* esq_p; cudaGetSymbolAddress((void**)&esq_p, g_esq);
    sqnorm_kernel<<<(N + 127) / 128, 128>>>(A, zsq_p, N);
    sqnorm_kernel<<<(K + 127) / 128, 128>>>(B, esq_p, K);

    __nv_bfloat16* Abf_p; cudaGetSymbolAddress((void**)&Abf_p, g_Abf);
    __nv_bfloat16* Bbf_p; cudaGetSymbolAddress((void**)&Bbf_p, g_Bbf);
    {
        size_t na = (size_t)N * DDIM;
        convert_kernel<<<(unsigned)((na / 4 + 255) / 256), 256>>>(A, Abf_p, na);
        size_t nb = (size_t)K * DDIM;
        convert_kernel<<<(unsigned)((nb / 4 + 255) / 256), 256>>>(B, Bbf_p, nb);
    }

    dim3 grid(N / BM, K / BN);   // (32, 512) — m fastest for B-strip L2 reuse
    pass1_kernel<<<grid, 256, SMEM_BYTES>>>();

    finalize_kernel<<<N, 256>>>(A, B, out_codes, out_q);
    loss_kernel<<<1, 32>>>(out_loss, 1.0 / ((double)N * (double)DDIM));
}